// round 7
// baseline (speedup 1.0000x reference)
#include <cuda_runtime.h>
#include <cuda_bf16.h>

#define BATCH 1024

// ---------------------------------------------------------------------------
__device__ float g_xt[3 * 32 * 32 * BATCH];   // (3,32,32,B)
__device__ float g_h1[6 * 14 * 14 * BATCH];   // conv1+relu+pool
__device__ float g_h2[16 * 5 * 5 * BATCH];    // conv2+relu+pool
__device__ float g_p3[20 * 120 * BATCH];      // conv3 K-split partials (20 way)
__device__ float g_h3[120 * BATCH];           // conv3+relu
__device__ float g_p4[5 * 84 * BATCH];        // fc2 K-split partials (5 way)

using u64 = unsigned long long;
struct __align__(16) U2 { u64 lo, hi; };

__device__ __forceinline__ u64 ffma2(u64 a, u64 b, u64 c) {
    u64 d;
    asm("fma.rn.f32x2 %0, %1, %2, %3;" : "=l"(d) : "l"(a), "l"(b), "l"(c));
    return d;
}
__device__ __forceinline__ u64 pk2(float x, float y) {
    u64 r; asm("mov.b64 %0, {%1, %2};" : "=l"(r) : "f"(x), "f"(y)); return r;
}
__device__ __forceinline__ float2 upk(u64 v) {
    float2 r; asm("mov.b64 {%0, %1}, %2;" : "=f"(r.x), "=f"(r.y) : "l"(v)); return r;
}

// ---------------------------------------------------------------------------
// Transpose x (B,3072) -> (3072,B)
// ---------------------------------------------------------------------------
__global__ __launch_bounds__(256) void k_transpose(const float* __restrict__ x) {
    __shared__ float t[32][133];
    int p0 = blockIdx.x * 128;
    int b0 = blockIdx.y * 32;
    int tx = threadIdx.x & 31, ty = threadIdx.x >> 5;
#pragma unroll
    for (int rr = 0; rr < 4; rr++) {
        int row = ty + 8 * rr;
        float4 v = *(const float4*)&x[(b0 + row) * 3072 + p0 + 4 * tx];
        t[row][4 * tx + 0] = v.x; t[row][4 * tx + 1] = v.y;
        t[row][4 * tx + 2] = v.z; t[row][4 * tx + 3] = v.w;
    }
    __syncthreads();
#pragma unroll
    for (int q = 0; q < 4; q++) {
        int idx = q * 256 + threadIdx.x;
        int pp = idx >> 3;
        int bg = idx & 7;
        float4 v = make_float4(t[4 * bg + 0][pp], t[4 * bg + 1][pp],
                               t[4 * bg + 2][pp], t[4 * bg + 3][pp]);
        *(float4*)&g_xt[(p0 + pp) * BATCH + b0 + 4 * bg] = v;
    }
}

// ---------------------------------------------------------------------------
// conv1: untied 5x5, 3->6, +relu+pool. o-tile 6 (NO og split -> activation
// traffic halved vs og2), thread = 2 images. Grid (196 loc, 2 bc) = 392 CTAs.
// ---------------------------------------------------------------------------
__global__ __launch_bounds__(256) void k_conv1(const float* __restrict__ w1,
                                               const float* __restrict__ b1) {
    __shared__ __align__(16) u64 ws[3][4][5][6][6];   // [c][pos][ky][o][kx]
    __shared__ float bs[6][4];
    int loc = blockIdx.x;
    int py = loc / 14, px = loc % 14;
    int tid = threadIdx.x;
    int b = (blockIdx.y * 256 + tid) * 2;

    for (int i = tid; i < 1800; i += 256) {
        int o = i / 300, r = i % 300;
        int pos = r / 75, r2 = r % 75;
        int c = r2 / 25, k = r2 % 25;
        int ky = k / 5, kx = k % 5;
        int ho = 2 * py + (pos >> 1), wo = 2 * px + (pos & 1);
        float w = w1[(((o * 3 + c) * 28 + ho) * 28 + wo) * 25 + k];
        ws[c][pos][ky][o][kx] = pk2(w, w);
    }
    if (tid < 24) {
        int o = tid / 4, pos = tid % 4;
        int ho = 2 * py + (pos >> 1), wo = 2 * px + (pos & 1);
        bs[o][pos] = b1[(o * 28 + ho) * 28 + wo];
    }
    __syncthreads();

    u64 acc[6][4];
#pragma unroll
    for (int i = 0; i < 24; i++) (&acc[0][0])[i] = 0ull;

    const float* base0 = &g_xt[((2 * py) * 32 + 2 * px) * BATCH + b];
    u64 abuf[2][6];
#pragma unroll
    for (int ix = 0; ix < 6; ix++) abuf[0][ix] = *(const u64*)&base0[ix * BATCH];

#pragma unroll 1
    for (int c = 0; c < 3; c++) {
        const float* base = base0 + c * (1024 * BATCH);
#pragma unroll
        for (int iy = 0; iy < 6; iy++) {
            int cur = iy & 1, nxt = cur ^ 1;
            const float* np = (iy < 5) ? base + (iy + 1) * (32 * BATCH)
                                       : base + ((c < 2) ? 1024 * BATCH : 0);
#pragma unroll
            for (int ix = 0; ix < 6; ix++) abuf[nxt][ix] = *(const u64*)&np[ix * BATCH];
#pragma unroll
            for (int dy = 0; dy < 2; dy++) {
                int ky = iy - dy;
                if (ky < 0 || ky > 4) continue;
#pragma unroll
                for (int o = 0; o < 6; o++)
#pragma unroll
                    for (int dx = 0; dx < 2; dx++) {
                        int pos = dy * 2 + dx;
                        U2 w01 = *(const U2*)&ws[c][pos][ky][o][0];
                        U2 w23 = *(const U2*)&ws[c][pos][ky][o][2];
                        u64 w4 = ws[c][pos][ky][o][4];
                        u64 a = acc[o][pos];
                        a = ffma2(w01.lo, abuf[cur][0 + dx], a);
                        a = ffma2(w01.hi, abuf[cur][1 + dx], a);
                        a = ffma2(w23.lo, abuf[cur][2 + dx], a);
                        a = ffma2(w23.hi, abuf[cur][3 + dx], a);
                        a = ffma2(w4,     abuf[cur][4 + dx], a);
                        acc[o][pos] = a;
                    }
            }
        }
    }
#pragma unroll
    for (int o = 0; o < 6; o++) {
        float2 a0 = upk(acc[o][0]), a1 = upk(acc[o][1]);
        float2 a2 = upk(acc[o][2]), a3 = upk(acc[o][3]);
        float b0v = bs[o][0], b1v = bs[o][1], b2v = bs[o][2], b3v = bs[o][3];
        float2 r;
        r.x = fmaxf(fmaxf(fmaxf(a0.x + b0v, a1.x + b1v), fmaxf(a2.x + b2v, a3.x + b3v)), 0.0f);
        r.y = fmaxf(fmaxf(fmaxf(a0.y + b0v, a1.y + b1v), fmaxf(a2.y + b2v, a3.y + b3v)), 0.0f);
        *(float2*)&g_h1[(o * 196 + loc) * BATCH + b] = r;
    }
}

// ---------------------------------------------------------------------------
// conv2: untied 5x5, 6->16, +relu+pool. o-tile 4 (og split 4 -> traffic
// halved vs og8), thread = 2 images. Grid (25 loc, 4 og, 2 bc) = 200 CTAs.
// ---------------------------------------------------------------------------
__global__ __launch_bounds__(256) void k_conv2(const float* __restrict__ w2,
                                               const float* __restrict__ b2) {
    __shared__ __align__(16) u64 ws[6][4][5][4][6];   // [c][pos][ky][o][kx]
    __shared__ float bs[4][4];
    int loc = blockIdx.x;
    int py = loc / 5, px = loc % 5;
    int og = blockIdx.y * 4;
    int tid = threadIdx.x;
    int b = (blockIdx.z * 256 + tid) * 2;

    for (int i = tid; i < 2400; i += 256) {
        int o = i / 600, r = i % 600;
        int pos = r / 150, r2 = r % 150;
        int c = r2 / 25, k = r2 % 25;
        int ky = k / 5, kx = k % 5;
        int ho = 2 * py + (pos >> 1), wo = 2 * px + (pos & 1);
        float w = w2[((((og + o) * 6 + c) * 10 + ho) * 10 + wo) * 25 + k];
        ws[c][pos][ky][o][kx] = pk2(w, w);
    }
    if (tid < 16) {
        int o = tid / 4, pos = tid % 4;
        int ho = 2 * py + (pos >> 1), wo = 2 * px + (pos & 1);
        bs[o][pos] = b2[((og + o) * 10 + ho) * 10 + wo];
    }
    __syncthreads();

    u64 acc[4][4];
#pragma unroll
    for (int i = 0; i < 16; i++) (&acc[0][0])[i] = 0ull;

    const float* base0 = &g_h1[((2 * py) * 14 + 2 * px) * BATCH + b];
    u64 abuf[2][6];
#pragma unroll
    for (int ix = 0; ix < 6; ix++) abuf[0][ix] = *(const u64*)&base0[ix * BATCH];

#pragma unroll 1
    for (int c = 0; c < 6; c++) {
        const float* base = base0 + c * (196 * BATCH);
#pragma unroll
        for (int iy = 0; iy < 6; iy++) {
            int cur = iy & 1, nxt = cur ^ 1;
            const float* np = (iy < 5) ? base + (iy + 1) * (14 * BATCH)
                                       : base + ((c < 5) ? 196 * BATCH : 0);
#pragma unroll
            for (int ix = 0; ix < 6; ix++) abuf[nxt][ix] = *(const u64*)&np[ix * BATCH];
#pragma unroll
            for (int dy = 0; dy < 2; dy++) {
                int ky = iy - dy;
                if (ky < 0 || ky > 4) continue;
#pragma unroll
                for (int o = 0; o < 4; o++)
#pragma unroll
                    for (int dx = 0; dx < 2; dx++) {
                        int pos = dy * 2 + dx;
                        U2 w01 = *(const U2*)&ws[c][pos][ky][o][0];
                        U2 w23 = *(const U2*)&ws[c][pos][ky][o][2];
                        u64 w4 = ws[c][pos][ky][o][4];
                        u64 a = acc[o][pos];
                        a = ffma2(w01.lo, abuf[cur][0 + dx], a);
                        a = ffma2(w01.hi, abuf[cur][1 + dx], a);
                        a = ffma2(w23.lo, abuf[cur][2 + dx], a);
                        a = ffma2(w23.hi, abuf[cur][3 + dx], a);
                        a = ffma2(w4,     abuf[cur][4 + dx], a);
                        acc[o][pos] = a;
                    }
            }
        }
    }
#pragma unroll
    for (int o = 0; o < 4; o++) {
        float2 a0 = upk(acc[o][0]), a1 = upk(acc[o][1]);
        float2 a2 = upk(acc[o][2]), a3 = upk(acc[o][3]);
        float2 r;
        r.x = fmaxf(fmaxf(fmaxf(a0.x + bs[o][0], a1.x + bs[o][1]),
                          fmaxf(a2.x + bs[o][2], a3.x + bs[o][3])), 0.0f);
        r.y = fmaxf(fmaxf(fmaxf(a0.y + bs[o][0], a1.y + bs[o][1]),
                          fmaxf(a2.y + bs[o][2], a3.y + bs[o][3])), 0.0f);
        *(float2*)&g_h2[((og + o) * 25 + loc) * BATCH + b] = r;
    }
}

// ---------------------------------------------------------------------------
// conv3 GEMM (120x1024x400): o-tile 8, K-split 20 (K=20), 256 thr, 2 img/thr.
// Grid (15, 20, 2) = 600 CTAs x 8 warps. Chunk-4 prefetch.
// ---------------------------------------------------------------------------
__global__ __launch_bounds__(256) void k_conv3(const float* __restrict__ w3) {
    __shared__ __align__(16) u64 ws[20][8];
    int og = blockIdx.x * 8;
    int k0 = blockIdx.y * 20;
    int tid = threadIdx.x;
    int b = (blockIdx.z * 256 + tid) * 2;

    if (tid < 160) {
        int o = tid & 7, k = tid >> 3;
        float w = w3[(og + o) * 400 + k0 + k];
        ws[k][o] = pk2(w, w);
    }
    __syncthreads();

    u64 acc[8];
#pragma unroll
    for (int o = 0; o < 8; o++) acc[o] = 0ull;

    const float* hp = &g_h2[k0 * BATCH + b];
    u64 abuf[2][4];
#pragma unroll
    for (int j = 0; j < 4; j++) abuf[0][j] = *(const u64*)&hp[j * BATCH];

#pragma unroll 1
    for (int kk = 0; kk < 5; kk++) {
        int cur = kk & 1, nxt = cur ^ 1;
        const float* np = hp + ((kk < 4) ? (kk + 1) * (4 * BATCH) : 0);
#pragma unroll
        for (int j = 0; j < 4; j++) abuf[nxt][j] = *(const u64*)&np[j * BATCH];
#pragma unroll
        for (int j = 0; j < 4; j++)
#pragma unroll
            for (int op = 0; op < 4; op++) {
                U2 wp = *(const U2*)&ws[kk * 4 + j][2 * op];
                acc[2 * op]     = ffma2(wp.lo, abuf[cur][j], acc[2 * op]);
                acc[2 * op + 1] = ffma2(wp.hi, abuf[cur][j], acc[2 * op + 1]);
            }
    }
#pragma unroll
    for (int o = 0; o < 8; o++)
        *(u64*)&g_p3[(blockIdx.y * 120 + og + o) * BATCH + b] = acc[o];
}

// h3 = relu(sum_20 partials + bias)
__global__ __launch_bounds__(128) void k_h3fix(const float* __restrict__ b3) {
    int i = blockIdx.x * 128 + threadIdx.x;   // float4 idx, 0..30719
    int o = i >> 8;
    float4 s = *(const float4*)&g_p3[i * 4];
#pragma unroll
    for (int p = 1; p < 20; p++) {
        float4 q = *(const float4*)&g_p3[p * 120 * BATCH + i * 4];
        s.x += q.x; s.y += q.y; s.z += q.z; s.w += q.w;
    }
    float bb = __ldg(&b3[o]);
    float4 r;
    r.x = fmaxf(s.x + bb, 0.0f);
    r.y = fmaxf(s.y + bb, 0.0f);
    r.z = fmaxf(s.z + bb, 0.0f);
    r.w = fmaxf(s.w + bb, 0.0f);
    *(float4*)&g_h3[i * 4] = r;
}

// ---------------------------------------------------------------------------
// fc2 GEMM (84x1024x120): o-tile 4, K-split 5 (K=24), 256 thr, 2 img/thr.
// Writes partials g_p4; fc3 folds the sum+bias+relu.
// ---------------------------------------------------------------------------
__global__ __launch_bounds__(256) void k_fc2(const float* __restrict__ fw) {
    __shared__ __align__(16) u64 ws[24][4];
    int og = blockIdx.x * 4;
    int k0 = blockIdx.y * 24;
    int tid = threadIdx.x;
    int b = (blockIdx.z * 256 + tid) * 2;

    if (tid < 96) {
        int o = tid & 3, k = tid >> 2;
        float w = fw[(og + o) * 120 + k0 + k];
        ws[k][o] = pk2(w, w);
    }
    __syncthreads();

    u64 acc[4];
#pragma unroll
    for (int o = 0; o < 4; o++) acc[o] = 0ull;

    const float* hp = &g_h3[k0 * BATCH + b];
    u64 abuf[2][8];
#pragma unroll
    for (int j = 0; j < 8; j++) abuf[0][j] = *(const u64*)&hp[j * BATCH];

#pragma unroll 1
    for (int kk = 0; kk < 3; kk++) {
        int cur = kk & 1, nxt = cur ^ 1;
        const float* np = hp + ((kk < 2) ? (kk + 1) * (8 * BATCH) : 0);
#pragma unroll
        for (int j = 0; j < 8; j++) abuf[nxt][j] = *(const u64*)&np[j * BATCH];
#pragma unroll
        for (int j = 0; j < 8; j++) {
            U2 w01 = *(const U2*)&ws[kk * 8 + j][0];
            U2 w23 = *(const U2*)&ws[kk * 8 + j][2];
            acc[0] = ffma2(w01.lo, abuf[cur][j], acc[0]);
            acc[1] = ffma2(w01.hi, abuf[cur][j], acc[1]);
            acc[2] = ffma2(w23.lo, abuf[cur][j], acc[2]);
            acc[3] = ffma2(w23.hi, abuf[cur][j], acc[3]);
        }
    }
#pragma unroll
    for (int o = 0; o < 4; o++)
        *(u64*)&g_p4[(blockIdx.y * 84 + og + o) * BATCH + b] = acc[o];
}

// ---------------------------------------------------------------------------
// fc3 (10x1024x84) + fused h4 reduction: h4[k][b] = relu(sum_5 p4 + fc2_b[k]).
// 32 CTAs x 160 thr = (5 o-pairs x 32 img). 84 = 7 x 12.
// ---------------------------------------------------------------------------
__global__ __launch_bounds__(160) void k_fc3(const float* __restrict__ fw,
                                             const float* __restrict__ fb,
                                             const float* __restrict__ fb2,
                                             float* __restrict__ out) {
    __shared__ u64 ws2[84][5];
    __shared__ float bsm[10];
    __shared__ float b2s[84];
    int tid = threadIdx.x;
    int p = tid >> 5;          // o-pair 0..4
    int img = tid & 31;
    int b = blockIdx.x * 32 + img;

    for (int i = tid; i < 420; i += 160) {
        int k = i / 5, q = i % 5;
        ws2[k][q] = pk2(fw[(2 * q) * 84 + k], fw[(2 * q + 1) * 84 + k]);
    }
    if (tid < 10) bsm[tid] = fb[tid];
    if (tid < 84) b2s[tid] = fb2[tid];
    __syncthreads();

    u64 acc = 0ull;
#pragma unroll 1
    for (int k0 = 0; k0 < 84; k0 += 12) {
        float t[5][12];
#pragma unroll
        for (int pp = 0; pp < 5; pp++)
#pragma unroll
            for (int j = 0; j < 12; j++)
                t[pp][j] = g_p4[(pp * 84 + k0 + j) * BATCH + b];
#pragma unroll
        for (int j = 0; j < 12; j++) {
            float v = fmaxf(t[0][j] + t[1][j] + t[2][j] + t[3][j] + t[4][j]
                            + b2s[k0 + j], 0.0f);
            acc = ffma2(ws2[k0 + j][p], pk2(v, v), acc);
        }
    }
    float2 r = upk(acc);
    out[b * 10 + 2 * p]     = r.x + bsm[2 * p];
    out[b * 10 + 2 * p + 1] = r.y + bsm[2 * p + 1];
}

// ---------------------------------------------------------------------------
extern "C" void kernel_launch(void* const* d_in, const int* in_sizes, int n_in,
                              void* d_out, int out_size) {
    (void)in_sizes; (void)n_in; (void)out_size;
    const float* x     = (const float*)d_in[0];
    const float* w1    = (const float*)d_in[1];
    const float* b1    = (const float*)d_in[2];
    const float* w2    = (const float*)d_in[3];
    const float* b2    = (const float*)d_in[4];
    const float* w3    = (const float*)d_in[5];
    const float* b3    = (const float*)d_in[6];
    const float* fc2_w = (const float*)d_in[7];
    const float* fc2_b = (const float*)d_in[8];
    const float* fc3_w = (const float*)d_in[9];
    const float* fc3_b = (const float*)d_in[10];
    float* out = (float*)d_out;

    k_transpose<<<dim3(24, 32), 256>>>(x);
    k_conv1<<<dim3(196, 2), 256>>>(w1, b1);
    k_conv2<<<dim3(25, 4, 2), 256>>>(w2, b2);
    k_conv3<<<dim3(15, 20, 2), 256>>>(w3);
    k_h3fix<<<240, 128>>>(b3);
    k_fc2<<<dim3(21, 5, 2), 256>>>(fc2_w);
    k_fc3<<<32, 160>>>(fc3_w, fc3_b, fc2_b, out);
}

// round 10
// speedup vs baseline: 1.2665x; 1.2665x over previous
#include <cuda_runtime.h>
#include <cuda_bf16.h>

#define BATCH 1024

// ---------------------------------------------------------------------------
__device__ float g_xt[3 * 32 * 32 * BATCH];   // (3,32,32,B)
__device__ float g_h1[6 * 14 * 14 * BATCH];   // conv1+relu+pool
__device__ float g_h2[16 * 5 * 5 * BATCH];    // conv2+relu+pool
__device__ float g_p3[20 * 120 * BATCH];      // conv3 K-split partials (20 way)
__device__ float g_h3[120 * BATCH];           // conv3+relu
__device__ float g_p4[5 * 84 * BATCH];        // fc2 K-split partials (5 way)

using u64 = unsigned long long;
struct __align__(16) U2 { u64 lo, hi; };

__device__ __forceinline__ u64 ffma2(u64 a, u64 b, u64 c) {
    u64 d;
    asm("fma.rn.f32x2 %0, %1, %2, %3;" : "=l"(d) : "l"(a), "l"(b), "l"(c));
    return d;
}
__device__ __forceinline__ u64 pk2(float x, float y) {
    u64 r; asm("mov.b64 %0, {%1, %2};" : "=l"(r) : "f"(x), "f"(y)); return r;
}
__device__ __forceinline__ float2 upk(u64 v) {
    float2 r; asm("mov.b64 {%0, %1}, %2;" : "=f"(r.x), "=f"(r.y) : "l"(v)); return r;
}

// ---------------------------------------------------------------------------
// Transpose x (B,3072) -> (3072,B)
// ---------------------------------------------------------------------------
__global__ __launch_bounds__(256) void k_transpose(const float* __restrict__ x) {
    __shared__ float t[32][133];
    int p0 = blockIdx.x * 128;
    int b0 = blockIdx.y * 32;
    int tx = threadIdx.x & 31, ty = threadIdx.x >> 5;
#pragma unroll
    for (int rr = 0; rr < 4; rr++) {
        int row = ty + 8 * rr;
        float4 v = *(const float4*)&x[(b0 + row) * 3072 + p0 + 4 * tx];
        t[row][4 * tx + 0] = v.x; t[row][4 * tx + 1] = v.y;
        t[row][4 * tx + 2] = v.z; t[row][4 * tx + 3] = v.w;
    }
    __syncthreads();
#pragma unroll
    for (int q = 0; q < 4; q++) {
        int idx = q * 256 + threadIdx.x;
        int pp = idx >> 3;
        int bg = idx & 7;
        float4 v = make_float4(t[4 * bg + 0][pp], t[4 * bg + 1][pp],
                               t[4 * bg + 2][pp], t[4 * bg + 3][pp]);
        *(float4*)&g_xt[(p0 + pp) * BATCH + b0 + 4 * bg] = v;
    }
}

// ---------------------------------------------------------------------------
// conv1 (R6): untied 5x5, 3->6, +relu+pool. o-tile 3, thread = 4 images.
// Grid (196 loc, 2 og) = 392 CTAs x 256 thr.
// ---------------------------------------------------------------------------
__global__ __launch_bounds__(256) void k_conv1(const float* __restrict__ w1,
                                               const float* __restrict__ b1) {
    __shared__ __align__(16) u64 ws[3][4][5][3][6];   // [c][pos][ky][o][kx]
    __shared__ float bs[3][4];
    int loc = blockIdx.x;
    int py = loc / 14, px = loc % 14;
    int og = blockIdx.y * 3;
    int tid = threadIdx.x;
    int b = tid * 4;

    for (int i = tid; i < 900; i += 256) {
        int o = i / 300, r = i % 300;
        int pos = r / 75, r2 = r % 75;
        int c = r2 / 25, k = r2 % 25;
        int ky = k / 5, kx = k % 5;
        int ho = 2 * py + (pos >> 1), wo = 2 * px + (pos & 1);
        float w = w1[((((og + o) * 3 + c) * 28 + ho) * 28 + wo) * 25 + k];
        ws[c][pos][ky][o][kx] = pk2(w, w);
    }
    if (tid < 12) {
        int o = tid / 4, pos = tid % 4;
        int ho = 2 * py + (pos >> 1), wo = 2 * px + (pos & 1);
        bs[o][pos] = b1[((og + o) * 28 + ho) * 28 + wo];
    }
    __syncthreads();

    u64 acc[3][4][2];
#pragma unroll
    for (int i = 0; i < 24; i++) (&acc[0][0][0])[i] = 0ull;

    const float* base0 = &g_xt[((2 * py) * 32 + 2 * px) * BATCH + b];
    U2 abuf[2][6];
#pragma unroll
    for (int ix = 0; ix < 6; ix++) abuf[0][ix] = *(const U2*)&base0[ix * BATCH];

#pragma unroll 1
    for (int c = 0; c < 3; c++) {
        const float* base = base0 + c * (1024 * BATCH);
#pragma unroll
        for (int iy = 0; iy < 6; iy++) {
            int cur = iy & 1, nxt = cur ^ 1;
            const float* np = (iy < 5) ? base + (iy + 1) * (32 * BATCH)
                                       : base + ((c < 2) ? 1024 * BATCH : 0);
#pragma unroll
            for (int ix = 0; ix < 6; ix++) abuf[nxt][ix] = *(const U2*)&np[ix * BATCH];
#pragma unroll
            for (int dy = 0; dy < 2; dy++) {
                int ky = iy - dy;
                if (ky < 0 || ky > 4) continue;
#pragma unroll
                for (int o = 0; o < 3; o++)
#pragma unroll
                    for (int dx = 0; dx < 2; dx++) {
                        int pos = dy * 2 + dx;
                        U2 w01 = *(const U2*)&ws[c][pos][ky][o][0];
                        U2 w23 = *(const U2*)&ws[c][pos][ky][o][2];
                        u64 w4 = ws[c][pos][ky][o][4];
                        u64* ap = &acc[o][pos][0];
                        ap[0] = ffma2(w01.lo, abuf[cur][0 + dx].lo, ap[0]);
                        ap[1] = ffma2(w01.lo, abuf[cur][0 + dx].hi, ap[1]);
                        ap[0] = ffma2(w01.hi, abuf[cur][1 + dx].lo, ap[0]);
                        ap[1] = ffma2(w01.hi, abuf[cur][1 + dx].hi, ap[1]);
                        ap[0] = ffma2(w23.lo, abuf[cur][2 + dx].lo, ap[0]);
                        ap[1] = ffma2(w23.lo, abuf[cur][2 + dx].hi, ap[1]);
                        ap[0] = ffma2(w23.hi, abuf[cur][3 + dx].lo, ap[0]);
                        ap[1] = ffma2(w23.hi, abuf[cur][3 + dx].hi, ap[1]);
                        ap[0] = ffma2(w4, abuf[cur][4 + dx].lo, ap[0]);
                        ap[1] = ffma2(w4, abuf[cur][4 + dx].hi, ap[1]);
                    }
            }
        }
    }
#pragma unroll
    for (int o = 0; o < 3; o++) {
        float2 a0 = upk(acc[o][0][0]), a1 = upk(acc[o][1][0]);
        float2 a2 = upk(acc[o][2][0]), a3 = upk(acc[o][3][0]);
        float2 c0 = upk(acc[o][0][1]), c1 = upk(acc[o][1][1]);
        float2 c2 = upk(acc[o][2][1]), c3 = upk(acc[o][3][1]);
        float b0v = bs[o][0], b1v = bs[o][1], b2v = bs[o][2], b3v = bs[o][3];
        float4 r;
        r.x = fmaxf(fmaxf(fmaxf(a0.x + b0v, a1.x + b1v), fmaxf(a2.x + b2v, a3.x + b3v)), 0.0f);
        r.y = fmaxf(fmaxf(fmaxf(a0.y + b0v, a1.y + b1v), fmaxf(a2.y + b2v, a3.y + b3v)), 0.0f);
        r.z = fmaxf(fmaxf(fmaxf(c0.x + b0v, c1.x + b1v), fmaxf(c2.x + b2v, c3.x + b3v)), 0.0f);
        r.w = fmaxf(fmaxf(fmaxf(c0.y + b0v, c1.y + b1v), fmaxf(c2.y + b2v, c3.y + b3v)), 0.0f);
        *(float4*)&g_h1[((og + o) * 196 + loc) * BATCH + b] = r;
    }
}

// ---------------------------------------------------------------------------
// conv2 (R6): untied 5x5, 6->16, +relu+pool. o-tile 2, thread = 4 images.
// Grid (25 loc, 8 og) = 200 CTAs x 256 thr.
// ---------------------------------------------------------------------------
__global__ __launch_bounds__(256) void k_conv2(const float* __restrict__ w2,
                                               const float* __restrict__ b2) {
    __shared__ __align__(16) u64 ws[6][4][5][2][6];
    __shared__ float bs[2][4];
    int loc = blockIdx.x;
    int py = loc / 5, px = loc % 5;
    int og = blockIdx.y * 2;
    int tid = threadIdx.x;
    int b = tid * 4;

    for (int i = tid; i < 1200; i += 256) {
        int o = i / 600, r = i % 600;
        int pos = r / 150, r2 = r % 150;
        int c = r2 / 25, k = r2 % 25;
        int ky = k / 5, kx = k % 5;
        int ho = 2 * py + (pos >> 1), wo = 2 * px + (pos & 1);
        float w = w2[((((og + o) * 6 + c) * 10 + ho) * 10 + wo) * 25 + k];
        ws[c][pos][ky][o][kx] = pk2(w, w);
    }
    if (tid < 8) {
        int o = tid / 4, pos = tid % 4;
        int ho = 2 * py + (pos >> 1), wo = 2 * px + (pos & 1);
        bs[o][pos] = b2[((og + o) * 10 + ho) * 10 + wo];
    }
    __syncthreads();

    u64 acc[2][4][2];
#pragma unroll
    for (int i = 0; i < 16; i++) (&acc[0][0][0])[i] = 0ull;

    const float* base0 = &g_h1[((2 * py) * 14 + 2 * px) * BATCH + b];
    U2 abuf[2][6];
#pragma unroll
    for (int ix = 0; ix < 6; ix++) abuf[0][ix] = *(const U2*)&base0[ix * BATCH];

#pragma unroll 1
    for (int c = 0; c < 6; c++) {
        const float* base = base0 + c * (196 * BATCH);
#pragma unroll
        for (int iy = 0; iy < 6; iy++) {
            int cur = iy & 1, nxt = cur ^ 1;
            const float* np = (iy < 5) ? base + (iy + 1) * (14 * BATCH)
                                       : base + ((c < 5) ? 196 * BATCH : 0);
#pragma unroll
            for (int ix = 0; ix < 6; ix++) abuf[nxt][ix] = *(const U2*)&np[ix * BATCH];
#pragma unroll
            for (int dy = 0; dy < 2; dy++) {
                int ky = iy - dy;
                if (ky < 0 || ky > 4) continue;
#pragma unroll
                for (int o = 0; o < 2; o++)
#pragma unroll
                    for (int dx = 0; dx < 2; dx++) {
                        int pos = dy * 2 + dx;
                        U2 w01 = *(const U2*)&ws[c][pos][ky][o][0];
                        U2 w23 = *(const U2*)&ws[c][pos][ky][o][2];
                        u64 w4 = ws[c][pos][ky][o][4];
                        u64* ap = &acc[o][pos][0];
                        ap[0] = ffma2(w01.lo, abuf[cur][0 + dx].lo, ap[0]);
                        ap[1] = ffma2(w01.lo, abuf[cur][0 + dx].hi, ap[1]);
                        ap[0] = ffma2(w01.hi, abuf[cur][1 + dx].lo, ap[0]);
                        ap[1] = ffma2(w01.hi, abuf[cur][1 + dx].hi, ap[1]);
                        ap[0] = ffma2(w23.lo, abuf[cur][2 + dx].lo, ap[0]);
                        ap[1] = ffma2(w23.lo, abuf[cur][2 + dx].hi, ap[1]);
                        ap[0] = ffma2(w23.hi, abuf[cur][3 + dx].lo, ap[0]);
                        ap[1] = ffma2(w23.hi, abuf[cur][3 + dx].hi, ap[1]);
                        ap[0] = ffma2(w4, abuf[cur][4 + dx].lo, ap[0]);
                        ap[1] = ffma2(w4, abuf[cur][4 + dx].hi, ap[1]);
                    }
            }
        }
    }
#pragma unroll
    for (int o = 0; o < 2; o++) {
        float2 a0 = upk(acc[o][0][0]), a1 = upk(acc[o][1][0]);
        float2 a2 = upk(acc[o][2][0]), a3 = upk(acc[o][3][0]);
        float2 c0 = upk(acc[o][0][1]), c1 = upk(acc[o][1][1]);
        float2 c2 = upk(acc[o][2][1]), c3 = upk(acc[o][3][1]);
        float b0v = bs[o][0], b1v = bs[o][1], b2v = bs[o][2], b3v = bs[o][3];
        float4 r;
        r.x = fmaxf(fmaxf(fmaxf(a0.x + b0v, a1.x + b1v), fmaxf(a2.x + b2v, a3.x + b3v)), 0.0f);
        r.y = fmaxf(fmaxf(fmaxf(a0.y + b0v, a1.y + b1v), fmaxf(a2.y + b2v, a3.y + b3v)), 0.0f);
        r.z = fmaxf(fmaxf(fmaxf(c0.x + b0v, c1.x + b1v), fmaxf(c2.x + b2v, c3.x + b3v)), 0.0f);
        r.w = fmaxf(fmaxf(fmaxf(c0.y + b0v, c1.y + b1v), fmaxf(c2.y + b2v, c3.y + b3v)), 0.0f);
        *(float4*)&g_h2[((og + o) * 25 + loc) * BATCH + b] = r;
    }
}

// ---------------------------------------------------------------------------
// conv3 GEMM (120x1024x400): o-tile 8, K-split 20 (K=20), 256 thr,
// thread = 4 images -> each weight LDS.128 feeds 4 FFMA2 (was 2).
// Grid (15, 20) = 300 CTAs x 8 warps, full batch per CTA.
// ---------------------------------------------------------------------------
__global__ __launch_bounds__(256) void k_conv3(const float* __restrict__ w3) {
    __shared__ __align__(16) u64 ws[20][8];
    int og = blockIdx.x * 8;
    int k0 = blockIdx.y * 20;
    int tid = threadIdx.x;
    int b = tid * 4;

    if (tid < 160) {
        int o = tid & 7, k = tid >> 3;
        float w = w3[(og + o) * 400 + k0 + k];
        ws[k][o] = pk2(w, w);
    }
    __syncthreads();

    u64 acc[8][2];
#pragma unroll
    for (int i = 0; i < 16; i++) (&acc[0][0])[i] = 0ull;

    const float* hp = &g_h2[k0 * BATCH + b];
    U2 abuf[2][4];
#pragma unroll
    for (int j = 0; j < 4; j++) abuf[0][j] = *(const U2*)&hp[j * BATCH];

#pragma unroll 1
    for (int kk = 0; kk < 5; kk++) {
        int cur = kk & 1, nxt = cur ^ 1;
        const float* np = hp + ((kk < 4) ? (kk + 1) * (4 * BATCH) : 0);
#pragma unroll
        for (int j = 0; j < 4; j++) abuf[nxt][j] = *(const U2*)&np[j * BATCH];
#pragma unroll
        for (int j = 0; j < 4; j++)
#pragma unroll
            for (int op = 0; op < 4; op++) {
                U2 wp = *(const U2*)&ws[kk * 4 + j][2 * op];
                acc[2 * op][0]     = ffma2(wp.lo, abuf[cur][j].lo, acc[2 * op][0]);
                acc[2 * op][1]     = ffma2(wp.lo, abuf[cur][j].hi, acc[2 * op][1]);
                acc[2 * op + 1][0] = ffma2(wp.hi, abuf[cur][j].lo, acc[2 * op + 1][0]);
                acc[2 * op + 1][1] = ffma2(wp.hi, abuf[cur][j].hi, acc[2 * op + 1][1]);
            }
    }
#pragma unroll
    for (int o = 0; o < 8; o++) {
        U2 r; r.lo = acc[o][0]; r.hi = acc[o][1];
        *(U2*)&g_p3[(blockIdx.y * 120 + og + o) * BATCH + b] = r;
    }
}

// h3 = relu(sum_20 partials + bias)
__global__ __launch_bounds__(128) void k_h3fix(const float* __restrict__ b3) {
    int i = blockIdx.x * 128 + threadIdx.x;   // float4 idx, 0..30719
    int o = i >> 8;
    float4 s = *(const float4*)&g_p3[i * 4];
#pragma unroll
    for (int p = 1; p < 20; p++) {
        float4 q = *(const float4*)&g_p3[p * 120 * BATCH + i * 4];
        s.x += q.x; s.y += q.y; s.z += q.z; s.w += q.w;
    }
    float bb = __ldg(&b3[o]);
    float4 r;
    r.x = fmaxf(s.x + bb, 0.0f);
    r.y = fmaxf(s.y + bb, 0.0f);
    r.z = fmaxf(s.z + bb, 0.0f);
    r.w = fmaxf(s.w + bb, 0.0f);
    *(float4*)&g_h3[i * 4] = r;
}

// ---------------------------------------------------------------------------
// fc2 GEMM (84x1024x120): o-tile 4, K-split 5 (K=24), 256 thr, 2 img/thr.
// Writes partials g_p4; fc3 folds the sum+bias+relu.
// ---------------------------------------------------------------------------
__global__ __launch_bounds__(256) void k_fc2(const float* __restrict__ fw) {
    __shared__ __align__(16) u64 ws[24][4];
    int og = blockIdx.x * 4;
    int k0 = blockIdx.y * 24;
    int tid = threadIdx.x;
    int b = (blockIdx.z * 256 + tid) * 2;

    if (tid < 96) {
        int o = tid & 3, k = tid >> 2;
        float w = fw[(og + o) * 120 + k0 + k];
        ws[k][o] = pk2(w, w);
    }
    __syncthreads();

    u64 acc[4];
#pragma unroll
    for (int o = 0; o < 4; o++) acc[o] = 0ull;

    const float* hp = &g_h3[k0 * BATCH + b];
    u64 abuf[2][8];
#pragma unroll
    for (int j = 0; j < 8; j++) abuf[0][j] = *(const u64*)&hp[j * BATCH];

#pragma unroll 1
    for (int kk = 0; kk < 3; kk++) {
        int cur = kk & 1, nxt = cur ^ 1;
        const float* np = hp + ((kk < 2) ? (kk + 1) * (8 * BATCH) : 0);
#pragma unroll
        for (int j = 0; j < 8; j++) abuf[nxt][j] = *(const u64*)&np[j * BATCH];
#pragma unroll
        for (int j = 0; j < 8; j++) {
            U2 w01 = *(const U2*)&ws[kk * 8 + j][0];
            U2 w23 = *(const U2*)&ws[kk * 8 + j][2];
            acc[0] = ffma2(w01.lo, abuf[cur][j], acc[0]);
            acc[1] = ffma2(w01.hi, abuf[cur][j], acc[1]);
            acc[2] = ffma2(w23.lo, abuf[cur][j], acc[2]);
            acc[3] = ffma2(w23.hi, abuf[cur][j], acc[3]);
        }
    }
#pragma unroll
    for (int o = 0; o < 4; o++)
        *(u64*)&g_p4[(blockIdx.y * 84 + og + o) * BATCH + b] = acc[o];
}

// ---------------------------------------------------------------------------
// fc3 (10x1024x84) + fused h4 reduction: h4[k][b] = relu(sum_5 p4 + fc2_b[k]).
// 32 CTAs x 160 thr = (5 o-pairs x 32 img).
// ---------------------------------------------------------------------------
__global__ __launch_bounds__(160) void k_fc3(const float* __restrict__ fw,
                                             const float* __restrict__ fb,
                                             const float* __restrict__ fb2,
                                             float* __restrict__ out) {
    __shared__ u64 ws2[84][5];
    __shared__ float bsm[10];
    __shared__ float b2s[84];
    int tid = threadIdx.x;
    int p = tid >> 5;          // o-pair 0..4
    int img = tid & 31;
    int b = blockIdx.x * 32 + img;

    for (int i = tid; i < 420; i += 160) {
        int k = i / 5, q = i % 5;
        ws2[k][q] = pk2(fw[(2 * q) * 84 + k], fw[(2 * q + 1) * 84 + k]);
    }
    if (tid < 10) bsm[tid] = fb[tid];
    if (tid < 84) b2s[tid] = fb2[tid];
    __syncthreads();

    u64 acc = 0ull;
#pragma unroll 1
    for (int k0 = 0; k0 < 84; k0 += 12) {
        float t[5][12];
#pragma unroll
        for (int pp = 0; pp < 5; pp++)
#pragma unroll
            for (int j = 0; j < 12; j++)
                t[pp][j] = g_p4[(pp * 84 + k0 + j) * BATCH + b];
#pragma unroll
        for (int j = 0; j < 12; j++) {
            float v = fmaxf(t[0][j] + t[1][j] + t[2][j] + t[3][j] + t[4][j]
                            + b2s[k0 + j], 0.0f);
            acc = ffma2(ws2[k0 + j][p], pk2(v, v), acc);
        }
    }
    float2 r = upk(acc);
    out[b * 10 + 2 * p]     = r.x + bsm[2 * p];
    out[b * 10 + 2 * p + 1] = r.y + bsm[2 * p + 1];
}

// ---------------------------------------------------------------------------
extern "C" void kernel_launch(void* const* d_in, const int* in_sizes, int n_in,
                              void* d_out, int out_size) {
    (void)in_sizes; (void)n_in; (void)out_size;
    const float* x     = (const float*)d_in[0];
    const float* w1    = (const float*)d_in[1];
    const float* b1    = (const float*)d_in[2];
    const float* w2    = (const float*)d_in[3];
    const float* b2    = (const float*)d_in[4];
    const float* w3    = (const float*)d_in[5];
    const float* b3    = (const float*)d_in[6];
    const float* fc2_w = (const float*)d_in[7];
    const float* fc2_b = (const float*)d_in[8];
    const float* fc3_w = (const float*)d_in[9];
    const float* fc3_b = (const float*)d_in[10];
    float* out = (float*)d_out;

    k_transpose<<<dim3(24, 32), 256>>>(x);
    k_conv1<<<dim3(196, 2), 256>>>(w1, b1);
    k_conv2<<<dim3(25, 8), 256>>>(w2, b2);
    k_conv3<<<dim3(15, 20), 256>>>(w3);
    k_h3fix<<<240, 128>>>(b3);
    k_fc2<<<dim3(21, 5, 2), 256>>>(fc2_w);
    k_fc3<<<32, 160>>>(fc3_w, fc3_b, fc2_b, out);
}

// round 12
// speedup vs baseline: 1.2969x; 1.0240x over previous
#include <cuda_runtime.h>
#include <cuda_bf16.h>

#define BATCH 1024

// ---------------------------------------------------------------------------
__device__ float g_xt[3 * 32 * 32 * BATCH];   // (3,32,32,B)
__device__ float g_h1[6 * 14 * 14 * BATCH];   // conv1+relu+pool
__device__ float g_h2[16 * 5 * 5 * BATCH];    // conv2+relu+pool
__device__ float g_p3[20 * 120 * BATCH];      // conv3 K-split partials (20 way)
__device__ float g_h3[120 * BATCH];           // conv3+relu
__device__ float g_p4[5 * 84 * BATCH];        // fc2 K-split partials (5 way)
__device__ float g_h4[84 * BATCH];            // fc2+relu

using u64 = unsigned long long;
struct __align__(16) U2 { u64 lo, hi; };

__device__ __forceinline__ u64 ffma2(u64 a, u64 b, u64 c) {
    u64 d;
    asm("fma.rn.f32x2 %0, %1, %2, %3;" : "=l"(d) : "l"(a), "l"(b), "l"(c));
    return d;
}
__device__ __forceinline__ u64 pk2(float x, float y) {
    u64 r; asm("mov.b64 %0, {%1, %2};" : "=l"(r) : "f"(x), "f"(y)); return r;
}
__device__ __forceinline__ float2 upk(u64 v) {
    float2 r; asm("mov.b64 {%0, %1}, %2;" : "=f"(r.x), "=f"(r.y) : "l"(v)); return r;
}

// ---------------------------------------------------------------------------
// Transpose x (B,3072) -> (3072,B)
// ---------------------------------------------------------------------------
__global__ __launch_bounds__(256) void k_transpose(const float* __restrict__ x) {
    __shared__ float t[32][133];
    int p0 = blockIdx.x * 128;
    int b0 = blockIdx.y * 32;
    int tx = threadIdx.x & 31, ty = threadIdx.x >> 5;
#pragma unroll
    for (int rr = 0; rr < 4; rr++) {
        int row = ty + 8 * rr;
        float4 v = *(const float4*)&x[(b0 + row) * 3072 + p0 + 4 * tx];
        t[row][4 * tx + 0] = v.x; t[row][4 * tx + 1] = v.y;
        t[row][4 * tx + 2] = v.z; t[row][4 * tx + 3] = v.w;
    }
    __syncthreads();
#pragma unroll
    for (int q = 0; q < 4; q++) {
        int idx = q * 256 + threadIdx.x;
        int pp = idx >> 3;
        int bg = idx & 7;
        float4 v = make_float4(t[4 * bg + 0][pp], t[4 * bg + 1][pp],
                               t[4 * bg + 2][pp], t[4 * bg + 3][pp]);
        *(float4*)&g_xt[(p0 + pp) * BATCH + b0 + 4 * bg] = v;
    }
}

// ---------------------------------------------------------------------------
// conv1: untied 5x5, 3->6, +relu+pool. o-tile 6 (NO og split -> half the
// activation traffic), thread = 4 images (4 FFMA2 per weight LDS pair).
// Grid 196 CTAs x 256 thr (full batch per CTA).
// ---------------------------------------------------------------------------
__global__ __launch_bounds__(256) void k_conv1(const float* __restrict__ w1,
                                               const float* __restrict__ b1) {
    __shared__ __align__(16) u64 ws[3][4][5][6][6];   // [c][pos][ky][o][kx]
    __shared__ float bs[6][4];
    int loc = blockIdx.x;
    int py = loc / 14, px = loc % 14;
    int tid = threadIdx.x;
    int b = tid * 4;

    for (int i = tid; i < 1800; i += 256) {
        int o = i / 300, r = i % 300;
        int pos = r / 75, r2 = r % 75;
        int c = r2 / 25, k = r2 % 25;
        int ky = k / 5, kx = k % 5;
        int ho = 2 * py + (pos >> 1), wo = 2 * px + (pos & 1);
        float w = w1[(((o * 3 + c) * 28 + ho) * 28 + wo) * 25 + k];
        ws[c][pos][ky][o][kx] = pk2(w, w);
    }
    if (tid < 24) {
        int o = tid / 4, pos = tid % 4;
        int ho = 2 * py + (pos >> 1), wo = 2 * px + (pos & 1);
        bs[o][pos] = b1[(o * 28 + ho) * 28 + wo];
    }
    __syncthreads();

    u64 acc[6][4][2];
#pragma unroll
    for (int i = 0; i < 48; i++) (&acc[0][0][0])[i] = 0ull;

    const float* base0 = &g_xt[((2 * py) * 32 + 2 * px) * BATCH + b];
    U2 abuf[2][6];
#pragma unroll
    for (int ix = 0; ix < 6; ix++) abuf[0][ix] = *(const U2*)&base0[ix * BATCH];

#pragma unroll 1
    for (int c = 0; c < 3; c++) {
        const float* base = base0 + c * (1024 * BATCH);
#pragma unroll
        for (int iy = 0; iy < 6; iy++) {
            int cur = iy & 1, nxt = cur ^ 1;
            const float* np = (iy < 5) ? base + (iy + 1) * (32 * BATCH)
                                       : base + ((c < 2) ? 1024 * BATCH : 0);
#pragma unroll
            for (int ix = 0; ix < 6; ix++) abuf[nxt][ix] = *(const U2*)&np[ix * BATCH];
#pragma unroll
            for (int dy = 0; dy < 2; dy++) {
                int ky = iy - dy;
                if (ky < 0 || ky > 4) continue;
#pragma unroll
                for (int o = 0; o < 6; o++)
#pragma unroll
                    for (int dx = 0; dx < 2; dx++) {
                        int pos = dy * 2 + dx;
                        U2 w01 = *(const U2*)&ws[c][pos][ky][o][0];
                        U2 w23 = *(const U2*)&ws[c][pos][ky][o][2];
                        u64 w4 = ws[c][pos][ky][o][4];
                        u64* ap = &acc[o][pos][0];
                        ap[0] = ffma2(w01.lo, abuf[cur][0 + dx].lo, ap[0]);
                        ap[1] = ffma2(w01.lo, abuf[cur][0 + dx].hi, ap[1]);
                        ap[0] = ffma2(w01.hi, abuf[cur][1 + dx].lo, ap[0]);
                        ap[1] = ffma2(w01.hi, abuf[cur][1 + dx].hi, ap[1]);
                        ap[0] = ffma2(w23.lo, abuf[cur][2 + dx].lo, ap[0]);
                        ap[1] = ffma2(w23.lo, abuf[cur][2 + dx].hi, ap[1]);
                        ap[0] = ffma2(w23.hi, abuf[cur][3 + dx].lo, ap[0]);
                        ap[1] = ffma2(w23.hi, abuf[cur][3 + dx].hi, ap[1]);
                        ap[0] = ffma2(w4, abuf[cur][4 + dx].lo, ap[0]);
                        ap[1] = ffma2(w4, abuf[cur][4 + dx].hi, ap[1]);
                    }
            }
        }
    }
#pragma unroll
    for (int o = 0; o < 6; o++) {
        float2 a0 = upk(acc[o][0][0]), a1 = upk(acc[o][1][0]);
        float2 a2 = upk(acc[o][2][0]), a3 = upk(acc[o][3][0]);
        float2 c0 = upk(acc[o][0][1]), c1 = upk(acc[o][1][1]);
        float2 c2 = upk(acc[o][2][1]), c3 = upk(acc[o][3][1]);
        float b0v = bs[o][0], b1v = bs[o][1], b2v = bs[o][2], b3v = bs[o][3];
        float4 r;
        r.x = fmaxf(fmaxf(fmaxf(a0.x + b0v, a1.x + b1v), fmaxf(a2.x + b2v, a3.x + b3v)), 0.0f);
        r.y = fmaxf(fmaxf(fmaxf(a0.y + b0v, a1.y + b1v), fmaxf(a2.y + b2v, a3.y + b3v)), 0.0f);
        r.z = fmaxf(fmaxf(fmaxf(c0.x + b0v, c1.x + b1v), fmaxf(c2.x + b2v, c3.x + b3v)), 0.0f);
        r.w = fmaxf(fmaxf(fmaxf(c0.y + b0v, c1.y + b1v), fmaxf(c2.y + b2v, c3.y + b3v)), 0.0f);
        *(float4*)&g_h1[(o * 196 + loc) * BATCH + b] = r;
    }
}

// ---------------------------------------------------------------------------
// conv2 (R6): untied 5x5, 6->16, +relu+pool. o-tile 2, thread = 4 images.
// Grid (25 loc, 8 og) = 200 CTAs x 256 thr.
// ---------------------------------------------------------------------------
__global__ __launch_bounds__(256) void k_conv2(const float* __restrict__ w2,
                                               const float* __restrict__ b2) {
    __shared__ __align__(16) u64 ws[6][4][5][2][6];
    __shared__ float bs[2][4];
    int loc = blockIdx.x;
    int py = loc / 5, px = loc % 5;
    int og = blockIdx.y * 2;
    int tid = threadIdx.x;
    int b = tid * 4;

    for (int i = tid; i < 1200; i += 256) {
        int o = i / 600, r = i % 600;
        int pos = r / 150, r2 = r % 150;
        int c = r2 / 25, k = r2 % 25;
        int ky = k / 5, kx = k % 5;
        int ho = 2 * py + (pos >> 1), wo = 2 * px + (pos & 1);
        float w = w2[((((og + o) * 6 + c) * 10 + ho) * 10 + wo) * 25 + k];
        ws[c][pos][ky][o][kx] = pk2(w, w);
    }
    if (tid < 8) {
        int o = tid / 4, pos = tid % 4;
        int ho = 2 * py + (pos >> 1), wo = 2 * px + (pos & 1);
        bs[o][pos] = b2[((og + o) * 10 + ho) * 10 + wo];
    }
    __syncthreads();

    u64 acc[2][4][2];
#pragma unroll
    for (int i = 0; i < 16; i++) (&acc[0][0][0])[i] = 0ull;

    const float* base0 = &g_h1[((2 * py) * 14 + 2 * px) * BATCH + b];
    U2 abuf[2][6];
#pragma unroll
    for (int ix = 0; ix < 6; ix++) abuf[0][ix] = *(const U2*)&base0[ix * BATCH];

#pragma unroll 1
    for (int c = 0; c < 6; c++) {
        const float* base = base0 + c * (196 * BATCH);
#pragma unroll
        for (int iy = 0; iy < 6; iy++) {
            int cur = iy & 1, nxt = cur ^ 1;
            const float* np = (iy < 5) ? base + (iy + 1) * (14 * BATCH)
                                       : base + ((c < 5) ? 196 * BATCH : 0);
#pragma unroll
            for (int ix = 0; ix < 6; ix++) abuf[nxt][ix] = *(const U2*)&np[ix * BATCH];
#pragma unroll
            for (int dy = 0; dy < 2; dy++) {
                int ky = iy - dy;
                if (ky < 0 || ky > 4) continue;
#pragma unroll
                for (int o = 0; o < 2; o++)
#pragma unroll
                    for (int dx = 0; dx < 2; dx++) {
                        int pos = dy * 2 + dx;
                        U2 w01 = *(const U2*)&ws[c][pos][ky][o][0];
                        U2 w23 = *(const U2*)&ws[c][pos][ky][o][2];
                        u64 w4 = ws[c][pos][ky][o][4];
                        u64* ap = &acc[o][pos][0];
                        ap[0] = ffma2(w01.lo, abuf[cur][0 + dx].lo, ap[0]);
                        ap[1] = ffma2(w01.lo, abuf[cur][0 + dx].hi, ap[1]);
                        ap[0] = ffma2(w01.hi, abuf[cur][1 + dx].lo, ap[0]);
                        ap[1] = ffma2(w01.hi, abuf[cur][1 + dx].hi, ap[1]);
                        ap[0] = ffma2(w23.lo, abuf[cur][2 + dx].lo, ap[0]);
                        ap[1] = ffma2(w23.lo, abuf[cur][2 + dx].hi, ap[1]);
                        ap[0] = ffma2(w23.hi, abuf[cur][3 + dx].lo, ap[0]);
                        ap[1] = ffma2(w23.hi, abuf[cur][3 + dx].hi, ap[1]);
                        ap[0] = ffma2(w4, abuf[cur][4 + dx].lo, ap[0]);
                        ap[1] = ffma2(w4, abuf[cur][4 + dx].hi, ap[1]);
                    }
            }
        }
    }
#pragma unroll
    for (int o = 0; o < 2; o++) {
        float2 a0 = upk(acc[o][0][0]), a1 = upk(acc[o][1][0]);
        float2 a2 = upk(acc[o][2][0]), a3 = upk(acc[o][3][0]);
        float2 c0 = upk(acc[o][0][1]), c1 = upk(acc[o][1][1]);
        float2 c2 = upk(acc[o][2][1]), c3 = upk(acc[o][3][1]);
        float b0v = bs[o][0], b1v = bs[o][1], b2v = bs[o][2], b3v = bs[o][3];
        float4 r;
        r.x = fmaxf(fmaxf(fmaxf(a0.x + b0v, a1.x + b1v), fmaxf(a2.x + b2v, a3.x + b3v)), 0.0f);
        r.y = fmaxf(fmaxf(fmaxf(a0.y + b0v, a1.y + b1v), fmaxf(a2.y + b2v, a3.y + b3v)), 0.0f);
        r.z = fmaxf(fmaxf(fmaxf(c0.x + b0v, c1.x + b1v), fmaxf(c2.x + b2v, c3.x + b3v)), 0.0f);
        r.w = fmaxf(fmaxf(fmaxf(c0.y + b0v, c1.y + b1v), fmaxf(c2.y + b2v, c3.y + b3v)), 0.0f);
        *(float4*)&g_h2[((og + o) * 25 + loc) * BATCH + b] = r;
    }
}

// ---------------------------------------------------------------------------
// conv3 GEMM (120x1024x400): o-tile 8, K-split 20 (K=20), 256 thr,
// thread = 4 images (4 FFMA2 per weight LDS pair). Grid (15, 20) = 300 CTAs.
// ---------------------------------------------------------------------------
__global__ __launch_bounds__(256) void k_conv3(const float* __restrict__ w3) {
    __shared__ __align__(16) u64 ws[20][8];
    int og = blockIdx.x * 8;
    int k0 = blockIdx.y * 20;
    int tid = threadIdx.x;
    int b = tid * 4;

    if (tid < 160) {
        int o = tid & 7, k = tid >> 3;
        float w = w3[(og + o) * 400 + k0 + k];
        ws[k][o] = pk2(w, w);
    }
    __syncthreads();

    u64 acc[8][2];
#pragma unroll
    for (int i = 0; i < 16; i++) (&acc[0][0])[i] = 0ull;

    const float* hp = &g_h2[k0 * BATCH + b];
    U2 abuf[2][4];
#pragma unroll
    for (int j = 0; j < 4; j++) abuf[0][j] = *(const U2*)&hp[j * BATCH];

#pragma unroll 1
    for (int kk = 0; kk < 5; kk++) {
        int cur = kk & 1, nxt = cur ^ 1;
        const float* np = hp + ((kk < 4) ? (kk + 1) * (4 * BATCH) : 0);
#pragma unroll
        for (int j = 0; j < 4; j++) abuf[nxt][j] = *(const U2*)&np[j * BATCH];
#pragma unroll
        for (int j = 0; j < 4; j++)
#pragma unroll
            for (int op = 0; op < 4; op++) {
                U2 wp = *(const U2*)&ws[kk * 4 + j][2 * op];
                acc[2 * op][0]     = ffma2(wp.lo, abuf[cur][j].lo, acc[2 * op][0]);
                acc[2 * op][1]     = ffma2(wp.lo, abuf[cur][j].hi, acc[2 * op][1]);
                acc[2 * op + 1][0] = ffma2(wp.hi, abuf[cur][j].lo, acc[2 * op + 1][0]);
                acc[2 * op + 1][1] = ffma2(wp.hi, abuf[cur][j].hi, acc[2 * op + 1][1]);
            }
    }
#pragma unroll
    for (int o = 0; o < 8; o++) {
        U2 r; r.lo = acc[o][0]; r.hi = acc[o][1];
        *(U2*)&g_p3[(blockIdx.y * 120 + og + o) * BATCH + b] = r;
    }
}

// h3 = relu(sum_20 partials + bias)
__global__ __launch_bounds__(128) void k_h3fix(const float* __restrict__ b3) {
    int i = blockIdx.x * 128 + threadIdx.x;   // float4 idx, 0..30719
    int o = i >> 8;
    float4 s = *(const float4*)&g_p3[i * 4];
#pragma unroll
    for (int p = 1; p < 20; p++) {
        float4 q = *(const float4*)&g_p3[p * 120 * BATCH + i * 4];
        s.x += q.x; s.y += q.y; s.z += q.z; s.w += q.w;
    }
    float bb = __ldg(&b3[o]);
    float4 r;
    r.x = fmaxf(s.x + bb, 0.0f);
    r.y = fmaxf(s.y + bb, 0.0f);
    r.z = fmaxf(s.z + bb, 0.0f);
    r.w = fmaxf(s.w + bb, 0.0f);
    *(float4*)&g_h3[i * 4] = r;
}

// ---------------------------------------------------------------------------
// fc2 GEMM (84x1024x120): o-tile 4, K-split 5 (K=24), 256 thr, 2 img/thr.
// ---------------------------------------------------------------------------
__global__ __launch_bounds__(256) void k_fc2(const float* __restrict__ fw) {
    __shared__ __align__(16) u64 ws[24][4];
    int og = blockIdx.x * 4;
    int k0 = blockIdx.y * 24;
    int tid = threadIdx.x;
    int b = (blockIdx.z * 256 + tid) * 2;

    if (tid < 96) {
        int o = tid & 3, k = tid >> 2;
        float w = fw[(og + o) * 120 + k0 + k];
        ws[k][o] = pk2(w, w);
    }
    __syncthreads();

    u64 acc[4];
#pragma unroll
    for (int o = 0; o < 4; o++) acc[o] = 0ull;

    const float* hp = &g_h3[k0 * BATCH + b];
    u64 abuf[2][8];
#pragma unroll
    for (int j = 0; j < 8; j++) abuf[0][j] = *(const u64*)&hp[j * BATCH];

#pragma unroll 1
    for (int kk = 0; kk < 3; kk++) {
        int cur = kk & 1, nxt = cur ^ 1;
        const float* np = hp + ((kk < 2) ? (kk + 1) * (8 * BATCH) : 0);
#pragma unroll
        for (int j = 0; j < 8; j++) abuf[nxt][j] = *(const u64*)&np[j * BATCH];
#pragma unroll
        for (int j = 0; j < 8; j++) {
            U2 w01 = *(const U2*)&ws[kk * 8 + j][0];
            U2 w23 = *(const U2*)&ws[kk * 8 + j][2];
            acc[0] = ffma2(w01.lo, abuf[cur][j], acc[0]);
            acc[1] = ffma2(w01.hi, abuf[cur][j], acc[1]);
            acc[2] = ffma2(w23.lo, abuf[cur][j], acc[2]);
            acc[3] = ffma2(w23.hi, abuf[cur][j], acc[3]);
        }
    }
#pragma unroll
    for (int o = 0; o < 4; o++)
        *(u64*)&g_p4[(blockIdx.y * 84 + og + o) * BATCH + b] = acc[o];
}

// h4 = relu(sum_5 partials + bias)
__global__ __launch_bounds__(128) void k_h4fix(const float* __restrict__ fb) {
    int i = blockIdx.x * 128 + threadIdx.x;   // float4 idx, 0..21503
    int o = i >> 8;
    float4 s = *(const float4*)&g_p4[i * 4];
#pragma unroll
    for (int p = 1; p < 5; p++) {
        float4 q = *(const float4*)&g_p4[p * 84 * BATCH + i * 4];
        s.x += q.x; s.y += q.y; s.z += q.z; s.w += q.w;
    }
    float bb = __ldg(&fb[o]);
    float4 r;
    r.x = fmaxf(s.x + bb, 0.0f);
    r.y = fmaxf(s.y + bb, 0.0f);
    r.z = fmaxf(s.z + bb, 0.0f);
    r.w = fmaxf(s.w + bb, 0.0f);
    *(float4*)&g_h4[i * 4] = r;
}

// ---------------------------------------------------------------------------
// fc3 (10x1024x84) -> out (B,10). 32 CTAs x 160 thr = (5 o-pairs x 32 img).
// ---------------------------------------------------------------------------
__global__ __launch_bounds__(160) void k_fc3(const float* __restrict__ fw,
                                             const float* __restrict__ fb,
                                             float* __restrict__ out) {
    __shared__ u64 ws2[84][5];
    __shared__ float bsm[10];
    int tid = threadIdx.x;
    int p = tid >> 5;          // o-pair 0..4
    int img = tid & 31;
    int b = blockIdx.x * 32 + img;

    for (int i = tid; i < 420; i += 160) {
        int k = i / 5, q = i % 5;
        ws2[k][q] = pk2(fw[(2 * q) * 84 + k], fw[(2 * q + 1) * 84 + k]);
    }
    if (tid < 10) bsm[tid] = fb[tid];
    __syncthreads();

    u64 acc = 0ull;
#pragma unroll 1
    for (int k0 = 0; k0 < 84; k0 += 12) {
        float v[12];
#pragma unroll
        for (int j = 0; j < 12; j++) v[j] = g_h4[(k0 + j) * BATCH + b];
#pragma unroll
        for (int j = 0; j < 12; j++)
            acc = ffma2(ws2[k0 + j][p], pk2(v[j], v[j]), acc);
    }
    float2 r = upk(acc);
    out[b * 10 + 2 * p]     = r.x + bsm[2 * p];
    out[b * 10 + 2 * p + 1] = r.y + bsm[2 * p + 1];
}

// ---------------------------------------------------------------------------
extern "C" void kernel_launch(void* const* d_in, const int* in_sizes, int n_in,
                              void* d_out, int out_size) {
    (void)in_sizes; (void)n_in; (void)out_size;
    const float* x     = (const float*)d_in[0];
    const float* w1    = (const float*)d_in[1];
    const float* b1    = (const float*)d_in[2];
    const float* w2    = (const float*)d_in[3];
    const float* b2    = (const float*)d_in[4];
    const float* w3    = (const float*)d_in[5];
    const float* b3    = (const float*)d_in[6];
    const float* fc2_w = (const float*)d_in[7];
    const float* fc2_b = (const float*)d_in[8];
    const float* fc3_w = (const float*)d_in[9];
    const float* fc3_b = (const float*)d_in[10];
    float* out = (float*)d_out;

    k_transpose<<<dim3(24, 32), 256>>>(x);
    k_conv1<<<196, 256>>>(w1, b1);
    k_conv2<<<dim3(25, 8), 256>>>(w2, b2);
    k_conv3<<<dim3(15, 20), 256>>>(w3);
    k_h3fix<<<240, 128>>>(b3);
    k_fc2<<<dim3(21, 5, 2), 256>>>(fc2_w);
    k_h4fix<<<168, 128>>>(fc2_b);
    k_fc3<<<32, 160>>>(fc3_w, fc3_b, out);
}

// round 13
// speedup vs baseline: 1.3998x; 1.0793x over previous
#include <cuda_runtime.h>
#include <cuda_bf16.h>

#define BATCH 1024

// ---------------------------------------------------------------------------
__device__ float g_xt[3 * 32 * 32 * BATCH];   // (3,32,32,B)
__device__ float g_h1[6 * 14 * 14 * BATCH];   // conv1+relu+pool
__device__ float g_h2[16 * 5 * 5 * BATCH];    // conv2+relu+pool
__device__ float g_p3[20 * 120 * BATCH];      // conv3 K-split partials (20 way)
__device__ float g_h3[120 * BATCH];           // conv3+relu
__device__ float g_p4[5 * 84 * BATCH];        // fc2 K-split partials (5 way)
__device__ float g_h4[84 * BATCH];            // fc2+relu

using u64 = unsigned long long;
struct __align__(16) U2 { u64 lo, hi; };

__device__ __forceinline__ u64 ffma2(u64 a, u64 b, u64 c) {
    u64 d;
    asm("fma.rn.f32x2 %0, %1, %2, %3;" : "=l"(d) : "l"(a), "l"(b), "l"(c));
    return d;
}
__device__ __forceinline__ u64 pk2(float x, float y) {
    u64 r; asm("mov.b64 %0, {%1, %2};" : "=l"(r) : "f"(x), "f"(y)); return r;
}
__device__ __forceinline__ float2 upk(u64 v) {
    float2 r; asm("mov.b64 {%0, %1}, %2;" : "=f"(r.x), "=f"(r.y) : "l"(v)); return r;
}

// ---------------------------------------------------------------------------
// Transpose x (B,3072) -> (3072,B)  [R6]
// ---------------------------------------------------------------------------
__global__ __launch_bounds__(256) void k_transpose(const float* __restrict__ x) {
    __shared__ float t[32][133];
    int p0 = blockIdx.x * 128;
    int b0 = blockIdx.y * 32;
    int tx = threadIdx.x & 31, ty = threadIdx.x >> 5;
#pragma unroll
    for (int rr = 0; rr < 4; rr++) {
        int row = ty + 8 * rr;
        float4 v = *(const float4*)&x[(b0 + row) * 3072 + p0 + 4 * tx];
        t[row][4 * tx + 0] = v.x; t[row][4 * tx + 1] = v.y;
        t[row][4 * tx + 2] = v.z; t[row][4 * tx + 3] = v.w;
    }
    __syncthreads();
#pragma unroll
    for (int q = 0; q < 4; q++) {
        int idx = q * 256 + threadIdx.x;
        int pp = idx >> 3;
        int bg = idx & 7;
        float4 v = make_float4(t[4 * bg + 0][pp], t[4 * bg + 1][pp],
                               t[4 * bg + 2][pp], t[4 * bg + 3][pp]);
        *(float4*)&g_xt[(p0 + pp) * BATCH + b0 + 4 * bg] = v;
    }
}

// ---------------------------------------------------------------------------
// conv1 [R6 best]: untied 5x5, 3->6, +relu+pool. o-tile 3, thread = 4 images.
// Grid (196 loc, 2 og) = 392 CTAs x 256 thr.
// ---------------------------------------------------------------------------
__global__ __launch_bounds__(256) void k_conv1(const float* __restrict__ w1,
                                               const float* __restrict__ b1) {
    __shared__ __align__(16) u64 ws[3][4][5][3][6];   // [c][pos][ky][o][kx]
    __shared__ float bs[3][4];
    int loc = blockIdx.x;
    int py = loc / 14, px = loc % 14;
    int og = blockIdx.y * 3;
    int tid = threadIdx.x;
    int b = tid * 4;

    for (int i = tid; i < 900; i += 256) {
        int o = i / 300, r = i % 300;
        int pos = r / 75, r2 = r % 75;
        int c = r2 / 25, k = r2 % 25;
        int ky = k / 5, kx = k % 5;
        int ho = 2 * py + (pos >> 1), wo = 2 * px + (pos & 1);
        float w = w1[((((og + o) * 3 + c) * 28 + ho) * 28 + wo) * 25 + k];
        ws[c][pos][ky][o][kx] = pk2(w, w);
    }
    if (tid < 12) {
        int o = tid / 4, pos = tid % 4;
        int ho = 2 * py + (pos >> 1), wo = 2 * px + (pos & 1);
        bs[o][pos] = b1[((og + o) * 28 + ho) * 28 + wo];
    }
    __syncthreads();

    u64 acc[3][4][2];
#pragma unroll
    for (int i = 0; i < 24; i++) (&acc[0][0][0])[i] = 0ull;

    const float* base0 = &g_xt[((2 * py) * 32 + 2 * px) * BATCH + b];
    U2 abuf[2][6];
#pragma unroll
    for (int ix = 0; ix < 6; ix++) abuf[0][ix] = *(const U2*)&base0[ix * BATCH];

#pragma unroll 1
    for (int c = 0; c < 3; c++) {
        const float* base = base0 + c * (1024 * BATCH);
#pragma unroll
        for (int iy = 0; iy < 6; iy++) {
            int cur = iy & 1, nxt = cur ^ 1;
            const float* np = (iy < 5) ? base + (iy + 1) * (32 * BATCH)
                                       : base + ((c < 2) ? 1024 * BATCH : 0);
#pragma unroll
            for (int ix = 0; ix < 6; ix++) abuf[nxt][ix] = *(const U2*)&np[ix * BATCH];
#pragma unroll
            for (int dy = 0; dy < 2; dy++) {
                int ky = iy - dy;
                if (ky < 0 || ky > 4) continue;
#pragma unroll
                for (int o = 0; o < 3; o++)
#pragma unroll
                    for (int dx = 0; dx < 2; dx++) {
                        int pos = dy * 2 + dx;
                        U2 w01 = *(const U2*)&ws[c][pos][ky][o][0];
                        U2 w23 = *(const U2*)&ws[c][pos][ky][o][2];
                        u64 w4 = ws[c][pos][ky][o][4];
                        u64* ap = &acc[o][pos][0];
                        ap[0] = ffma2(w01.lo, abuf[cur][0 + dx].lo, ap[0]);
                        ap[1] = ffma2(w01.lo, abuf[cur][0 + dx].hi, ap[1]);
                        ap[0] = ffma2(w01.hi, abuf[cur][1 + dx].lo, ap[0]);
                        ap[1] = ffma2(w01.hi, abuf[cur][1 + dx].hi, ap[1]);
                        ap[0] = ffma2(w23.lo, abuf[cur][2 + dx].lo, ap[0]);
                        ap[1] = ffma2(w23.lo, abuf[cur][2 + dx].hi, ap[1]);
                        ap[0] = ffma2(w23.hi, abuf[cur][3 + dx].lo, ap[0]);
                        ap[1] = ffma2(w23.hi, abuf[cur][3 + dx].hi, ap[1]);
                        ap[0] = ffma2(w4, abuf[cur][4 + dx].lo, ap[0]);
                        ap[1] = ffma2(w4, abuf[cur][4 + dx].hi, ap[1]);
                    }
            }
        }
    }
#pragma unroll
    for (int o = 0; o < 3; o++) {
        float2 a0 = upk(acc[o][0][0]), a1 = upk(acc[o][1][0]);
        float2 a2 = upk(acc[o][2][0]), a3 = upk(acc[o][3][0]);
        float2 c0 = upk(acc[o][0][1]), c1 = upk(acc[o][1][1]);
        float2 c2 = upk(acc[o][2][1]), c3 = upk(acc[o][3][1]);
        float b0v = bs[o][0], b1v = bs[o][1], b2v = bs[o][2], b3v = bs[o][3];
        float4 r;
        r.x = fmaxf(fmaxf(fmaxf(a0.x + b0v, a1.x + b1v), fmaxf(a2.x + b2v, a3.x + b3v)), 0.0f);
        r.y = fmaxf(fmaxf(fmaxf(a0.y + b0v, a1.y + b1v), fmaxf(a2.y + b2v, a3.y + b3v)), 0.0f);
        r.z = fmaxf(fmaxf(fmaxf(c0.x + b0v, c1.x + b1v), fmaxf(c2.x + b2v, c3.x + b3v)), 0.0f);
        r.w = fmaxf(fmaxf(fmaxf(c0.y + b0v, c1.y + b1v), fmaxf(c2.y + b2v, c3.y + b3v)), 0.0f);
        *(float4*)&g_h1[((og + o) * 196 + loc) * BATCH + b] = r;
    }
}

// ---------------------------------------------------------------------------
// conv2 [R6 best]: untied 5x5, 6->16, +relu+pool. o-tile 2, thread = 4 images.
// Grid (25 loc, 8 og) = 200 CTAs x 256 thr.
// ---------------------------------------------------------------------------
__global__ __launch_bounds__(256) void k_conv2(const float* __restrict__ w2,
                                               const float* __restrict__ b2) {
    __shared__ __align__(16) u64 ws[6][4][5][2][6];
    __shared__ float bs[2][4];
    int loc = blockIdx.x;
    int py = loc / 5, px = loc % 5;
    int og = blockIdx.y * 2;
    int tid = threadIdx.x;
    int b = tid * 4;

    for (int i = tid; i < 1200; i += 256) {
        int o = i / 600, r = i % 600;
        int pos = r / 150, r2 = r % 150;
        int c = r2 / 25, k = r2 % 25;
        int ky = k / 5, kx = k % 5;
        int ho = 2 * py + (pos >> 1), wo = 2 * px + (pos & 1);
        float w = w2[((((og + o) * 6 + c) * 10 + ho) * 10 + wo) * 25 + k];
        ws[c][pos][ky][o][kx] = pk2(w, w);
    }
    if (tid < 8) {
        int o = tid / 4, pos = tid % 4;
        int ho = 2 * py + (pos >> 1), wo = 2 * px + (pos & 1);
        bs[o][pos] = b2[((og + o) * 10 + ho) * 10 + wo];
    }
    __syncthreads();

    u64 acc[2][4][2];
#pragma unroll
    for (int i = 0; i < 16; i++) (&acc[0][0][0])[i] = 0ull;

    const float* base0 = &g_h1[((2 * py) * 14 + 2 * px) * BATCH + b];
    U2 abuf[2][6];
#pragma unroll
    for (int ix = 0; ix < 6; ix++) abuf[0][ix] = *(const U2*)&base0[ix * BATCH];

#pragma unroll 1
    for (int c = 0; c < 6; c++) {
        const float* base = base0 + c * (196 * BATCH);
#pragma unroll
        for (int iy = 0; iy < 6; iy++) {
            int cur = iy & 1, nxt = cur ^ 1;
            const float* np = (iy < 5) ? base + (iy + 1) * (14 * BATCH)
                                       : base + ((c < 5) ? 196 * BATCH : 0);
#pragma unroll
            for (int ix = 0; ix < 6; ix++) abuf[nxt][ix] = *(const U2*)&np[ix * BATCH];
#pragma unroll
            for (int dy = 0; dy < 2; dy++) {
                int ky = iy - dy;
                if (ky < 0 || ky > 4) continue;
#pragma unroll
                for (int o = 0; o < 2; o++)
#pragma unroll
                    for (int dx = 0; dx < 2; dx++) {
                        int pos = dy * 2 + dx;
                        U2 w01 = *(const U2*)&ws[c][pos][ky][o][0];
                        U2 w23 = *(const U2*)&ws[c][pos][ky][o][2];
                        u64 w4 = ws[c][pos][ky][o][4];
                        u64* ap = &acc[o][pos][0];
                        ap[0] = ffma2(w01.lo, abuf[cur][0 + dx].lo, ap[0]);
                        ap[1] = ffma2(w01.lo, abuf[cur][0 + dx].hi, ap[1]);
                        ap[0] = ffma2(w01.hi, abuf[cur][1 + dx].lo, ap[0]);
                        ap[1] = ffma2(w01.hi, abuf[cur][1 + dx].hi, ap[1]);
                        ap[0] = ffma2(w23.lo, abuf[cur][2 + dx].lo, ap[0]);
                        ap[1] = ffma2(w23.lo, abuf[cur][2 + dx].hi, ap[1]);
                        ap[0] = ffma2(w23.hi, abuf[cur][3 + dx].lo, ap[0]);
                        ap[1] = ffma2(w23.hi, abuf[cur][3 + dx].hi, ap[1]);
                        ap[0] = ffma2(w4, abuf[cur][4 + dx].lo, ap[0]);
                        ap[1] = ffma2(w4, abuf[cur][4 + dx].hi, ap[1]);
                    }
            }
        }
    }
#pragma unroll
    for (int o = 0; o < 2; o++) {
        float2 a0 = upk(acc[o][0][0]), a1 = upk(acc[o][1][0]);
        float2 a2 = upk(acc[o][2][0]), a3 = upk(acc[o][3][0]);
        float2 c0 = upk(acc[o][0][1]), c1 = upk(acc[o][1][1]);
        float2 c2 = upk(acc[o][2][1]), c3 = upk(acc[o][3][1]);
        float b0v = bs[o][0], b1v = bs[o][1], b2v = bs[o][2], b3v = bs[o][3];
        float4 r;
        r.x = fmaxf(fmaxf(fmaxf(a0.x + b0v, a1.x + b1v), fmaxf(a2.x + b2v, a3.x + b3v)), 0.0f);
        r.y = fmaxf(fmaxf(fmaxf(a0.y + b0v, a1.y + b1v), fmaxf(a2.y + b2v, a3.y + b3v)), 0.0f);
        r.z = fmaxf(fmaxf(fmaxf(c0.x + b0v, c1.x + b1v), fmaxf(c2.x + b2v, c3.x + b3v)), 0.0f);
        r.w = fmaxf(fmaxf(fmaxf(c0.y + b0v, c1.y + b1v), fmaxf(c2.y + b2v, c3.y + b3v)), 0.0f);
        *(float4*)&g_h2[((og + o) * 25 + loc) * BATCH + b] = r;
    }
}

// ---------------------------------------------------------------------------
// conv3 [R12 best]: GEMM (120x1024x400). o-tile 8, K-split 20 (K=20),
// 256 thr, thread = 4 images. Grid (15, 20) = 300 CTAs.
// ---------------------------------------------------------------------------
__global__ __launch_bounds__(256) void k_conv3(const float* __restrict__ w3) {
    __shared__ __align__(16) u64 ws[20][8];
    int og = blockIdx.x * 8;
    int k0 = blockIdx.y * 20;
    int tid = threadIdx.x;
    int b = tid * 4;

    if (tid < 160) {
        int o = tid & 7, k = tid >> 3;
        float w = w3[(og + o) * 400 + k0 + k];
        ws[k][o] = pk2(w, w);
    }
    __syncthreads();

    u64 acc[8][2];
#pragma unroll
    for (int i = 0; i < 16; i++) (&acc[0][0])[i] = 0ull;

    const float* hp = &g_h2[k0 * BATCH + b];
    U2 abuf[2][4];
#pragma unroll
    for (int j = 0; j < 4; j++) abuf[0][j] = *(const U2*)&hp[j * BATCH];

#pragma unroll 1
    for (int kk = 0; kk < 5; kk++) {
        int cur = kk & 1, nxt = cur ^ 1;
        const float* np = hp + ((kk < 4) ? (kk + 1) * (4 * BATCH) : 0);
#pragma unroll
        for (int j = 0; j < 4; j++) abuf[nxt][j] = *(const U2*)&np[j * BATCH];
#pragma unroll
        for (int j = 0; j < 4; j++)
#pragma unroll
            for (int op = 0; op < 4; op++) {
                U2 wp = *(const U2*)&ws[kk * 4 + j][2 * op];
                acc[2 * op][0]     = ffma2(wp.lo, abuf[cur][j].lo, acc[2 * op][0]);
                acc[2 * op][1]     = ffma2(wp.lo, abuf[cur][j].hi, acc[2 * op][1]);
                acc[2 * op + 1][0] = ffma2(wp.hi, abuf[cur][j].lo, acc[2 * op + 1][0]);
                acc[2 * op + 1][1] = ffma2(wp.hi, abuf[cur][j].hi, acc[2 * op + 1][1]);
            }
    }
#pragma unroll
    for (int o = 0; o < 8; o++) {
        U2 r; r.lo = acc[o][0]; r.hi = acc[o][1];
        *(U2*)&g_p3[(blockIdx.y * 120 + og + o) * BATCH + b] = r;
    }
}

// h3 = relu(sum_20 partials + bias)  [R6]
__global__ __launch_bounds__(128) void k_h3fix(const float* __restrict__ b3) {
    int i = blockIdx.x * 128 + threadIdx.x;   // float4 idx, 0..30719
    int o = i >> 8;
    float4 s = *(const float4*)&g_p3[i * 4];
#pragma unroll
    for (int p = 1; p < 20; p++) {
        float4 q = *(const float4*)&g_p3[p * 120 * BATCH + i * 4];
        s.x += q.x; s.y += q.y; s.z += q.z; s.w += q.w;
    }
    float bb = __ldg(&b3[o]);
    float4 r;
    r.x = fmaxf(s.x + bb, 0.0f);
    r.y = fmaxf(s.y + bb, 0.0f);
    r.z = fmaxf(s.z + bb, 0.0f);
    r.w = fmaxf(s.w + bb, 0.0f);
    *(float4*)&g_h3[i * 4] = r;
}

// ---------------------------------------------------------------------------
// fc2 [R6]: GEMM (84x1024x120). o-tile 4, K-split 5 (K=24), 256 thr, 2 img/thr.
// Grid (21, 5, 2) = 210 CTAs.
// ---------------------------------------------------------------------------
__global__ __launch_bounds__(256) void k_fc2(const float* __restrict__ fw) {
    __shared__ __align__(16) u64 ws[24][4];
    int og = blockIdx.x * 4;
    int k0 = blockIdx.y * 24;
    int tid = threadIdx.x;
    int b = (blockIdx.z * 256 + tid) * 2;

    if (tid < 96) {
        int o = tid & 3, k = tid >> 2;
        float w = fw[(og + o) * 120 + k0 + k];
        ws[k][o] = pk2(w, w);
    }
    __syncthreads();

    u64 acc[4];
#pragma unroll
    for (int o = 0; o < 4; o++) acc[o] = 0ull;

    const float* hp = &g_h3[k0 * BATCH + b];
    u64 abuf[2][8];
#pragma unroll
    for (int j = 0; j < 8; j++) abuf[0][j] = *(const u64*)&hp[j * BATCH];

#pragma unroll 1
    for (int kk = 0; kk < 3; kk++) {
        int cur = kk & 1, nxt = cur ^ 1;
        const float* np = hp + ((kk < 2) ? (kk + 1) * (8 * BATCH) : 0);
#pragma unroll
        for (int j = 0; j < 8; j++) abuf[nxt][j] = *(const u64*)&np[j * BATCH];
#pragma unroll
        for (int j = 0; j < 8; j++) {
            U2 w01 = *(const U2*)&ws[kk * 8 + j][0];
            U2 w23 = *(const U2*)&ws[kk * 8 + j][2];
            acc[0] = ffma2(w01.lo, abuf[cur][j], acc[0]);
            acc[1] = ffma2(w01.hi, abuf[cur][j], acc[1]);
            acc[2] = ffma2(w23.lo, abuf[cur][j], acc[2]);
            acc[3] = ffma2(w23.hi, abuf[cur][j], acc[3]);
        }
    }
#pragma unroll
    for (int o = 0; o < 4; o++)
        *(u64*)&g_p4[(blockIdx.y * 84 + og + o) * BATCH + b] = acc[o];
}

// h4 = relu(sum_5 partials + bias)  [R6]
__global__ __launch_bounds__(128) void k_h4fix(const float* __restrict__ fb) {
    int i = blockIdx.x * 128 + threadIdx.x;   // float4 idx, 0..21503
    int o = i >> 8;
    float4 s = *(const float4*)&g_p4[i * 4];
#pragma unroll
    for (int p = 1; p < 5; p++) {
        float4 q = *(const float4*)&g_p4[p * 84 * BATCH + i * 4];
        s.x += q.x; s.y += q.y; s.z += q.z; s.w += q.w;
    }
    float bb = __ldg(&fb[o]);
    float4 r;
    r.x = fmaxf(s.x + bb, 0.0f);
    r.y = fmaxf(s.y + bb, 0.0f);
    r.z = fmaxf(s.z + bb, 0.0f);
    r.w = fmaxf(s.w + bb, 0.0f);
    *(float4*)&g_h4[i * 4] = r;
}

// ---------------------------------------------------------------------------
// fc3 [R6]: (10x1024x84) -> out (B,10). 32 CTAs x 160 thr (5 o-pairs x 32 img).
// ---------------------------------------------------------------------------
__global__ __launch_bounds__(160) void k_fc3(const float* __restrict__ fw,
                                             const float* __restrict__ fb,
                                             float* __restrict__ out) {
    __shared__ u64 ws2[84][5];
    __shared__ float bsm[10];
    int tid = threadIdx.x;
    int p = tid >> 5;          // o-pair 0..4
    int img = tid & 31;
    int b = blockIdx.x * 32 + img;

    for (int i = tid; i < 420; i += 160) {
        int k = i / 5, q = i % 5;
        ws2[k][q] = pk2(fw[(2 * q) * 84 + k], fw[(2 * q + 1) * 84 + k]);
    }
    if (tid < 10) bsm[tid] = fb[tid];
    __syncthreads();

    u64 acc = 0ull;
#pragma unroll 1
    for (int k0 = 0; k0 < 84; k0 += 12) {
        float v[12];
#pragma unroll
        for (int j = 0; j < 12; j++) v[j] = g_h4[(k0 + j) * BATCH + b];
#pragma unroll
        for (int j = 0; j < 12; j++)
            acc = ffma2(ws2[k0 + j][p], pk2(v[j], v[j]), acc);
    }
    float2 r = upk(acc);
    out[b * 10 + 2 * p]     = r.x + bsm[2 * p];
    out[b * 10 + 2 * p + 1] = r.y + bsm[2 * p + 1];
}

// ---------------------------------------------------------------------------
extern "C" void kernel_launch(void* const* d_in, const int* in_sizes, int n_in,
                              void* d_out, int out_size) {
    (void)in_sizes; (void)n_in; (void)out_size;
    const float* x     = (const float*)d_in[0];
    const float* w1    = (const float*)d_in[1];
    const float* b1    = (const float*)d_in[2];
    const float* w2    = (const float*)d_in[3];
    const float* b2    = (const float*)d_in[4];
    const float* w3    = (const float*)d_in[5];
    const float* b3    = (const float*)d_in[6];
    const float* fc2_w = (const float*)d_in[7];
    const float* fc2_b = (const float*)d_in[8];
    const float* fc3_w = (const float*)d_in[9];
    const float* fc3_b = (const float*)d_in[10];
    float* out = (float*)d_out;

    k_transpose<<<dim3(24, 32), 256>>>(x);
    k_conv1<<<dim3(196, 2), 256>>>(w1, b1);
    k_conv2<<<dim3(25, 8), 256>>>(w2, b2);
    k_conv3<<<dim3(15, 20), 256>>>(w3);
    k_h3fix<<<240, 128>>>(b3);
    k_fc2<<<dim3(21, 5, 2), 256>>>(fc2_w);
    k_h4fix<<<168, 128>>>(fc2_b);
    k_fc3<<<32, 160>>>(fc3_w, fc3_b, out);
}